// round 15
// baseline (speedup 1.0000x reference)
#include <cuda_runtime.h>
#include <math.h>

#define NHEADS 12
#define HDIM   64
#define BATCH  4
#define SEQ    1024
#define HID    768

// Scratch for projected Q/K/V in [B, h, S, d] layout
__device__ float g_q[BATCH * NHEADS * SEQ * HDIM];
__device__ float g_k[BATCH * NHEADS * SEQ * HDIM];
__device__ float g_v[BATCH * NHEADS * SEQ * HDIM];

// ---------------------------------------------------------------------------
// Packed f32x2 helpers (Blackwell FFMA2 path — PTX only).
// Packed pair carried as unsigned long long (the "l" constraint is integer).
// ---------------------------------------------------------------------------
typedef unsigned long long pf2;

__device__ __forceinline__ pf2 ffma2(pf2 a, pf2 b, pf2 c) {
    pf2 d; asm("fma.rn.f32x2 %0, %1, %2, %3;" : "=l"(d) : "l"(a), "l"(b), "l"(c)); return d;
}
__device__ __forceinline__ pf2 mul2(pf2 a, pf2 b) {
    pf2 d; asm("mul.rn.f32x2 %0, %1, %2;" : "=l"(d) : "l"(a), "l"(b)); return d;
}
__device__ __forceinline__ pf2 pack2(float lo, float hi) {
    pf2 d; asm("mov.b64 %0, {%1, %2};" : "=l"(d) : "f"(lo), "f"(hi)); return d;
}
__device__ __forceinline__ void unpack2(pf2 d, float& lo, float& hi) {
    asm("mov.b64 {%0, %1}, %2;" : "=f"(lo), "=f"(hi) : "l"(d));
}

// ---------------------------------------------------------------------------
// QKV projection: out[n, m] = sum_k X[n,k] * W[m,k] + b[m]
// 128x128 tile, K-step 16, 256 threads, 8x8 micro-tile, f32x2 packed FMA.
// ---------------------------------------------------------------------------
__global__ __launch_bounds__(256) void qkv_proj_kernel(
    const float* __restrict__ X,
    const float* __restrict__ Wq, const float* __restrict__ bq,
    const float* __restrict__ Wk, const float* __restrict__ bk,
    const float* __restrict__ Wv, const float* __restrict__ bv)
{
    __shared__ float Xs[16][132];
    __shared__ float Ws[16][132];

    const int z = blockIdx.z;
    const float* __restrict__ W    = (z == 0) ? Wq : ((z == 1) ? Wk : Wv);
    const float* __restrict__ bias = (z == 0) ? bq : ((z == 1) ? bk : bv);
    float* __restrict__ out        = (z == 0) ? g_q : ((z == 1) ? g_k : g_v);

    const int n0 = blockIdx.x * 128;
    const int m0 = blockIdx.y * 128;
    const int t  = threadIdx.x;
    const int tn = t & 15;
    const int tm = t >> 4;

    pf2 acc2[8][4];   // [i][m-pair]; 0ull == (0f, 0f)
#pragma unroll
    for (int i = 0; i < 8; i++)
#pragma unroll
        for (int jp = 0; jp < 4; jp++) acc2[i][jp] = 0ull;

    for (int k0 = 0; k0 < HID; k0 += 16) {
#pragma unroll
        for (int it = 0; it < 2; ++it) {
            int id  = t + it * 256;
            int row = id >> 2;
            int kq  = (id & 3) << 2;
            float4 xv = *(const float4*)(X + (size_t)(n0 + row) * HID + k0 + kq);
            Xs[kq + 0][row] = xv.x; Xs[kq + 1][row] = xv.y;
            Xs[kq + 2][row] = xv.z; Xs[kq + 3][row] = xv.w;
            float4 wv = *(const float4*)(W + (size_t)(m0 + row) * HID + k0 + kq);
            Ws[kq + 0][row] = wv.x; Ws[kq + 1][row] = wv.y;
            Ws[kq + 2][row] = wv.z; Ws[kq + 3][row] = wv.w;
        }
        __syncthreads();

#pragma unroll
        for (int kk = 0; kk < 16; ++kk) {
            float xv[8];
            *(float4*)(xv)     = *(const float4*)(&Xs[kk][8 * tn]);
            *(float4*)(xv + 4) = *(const float4*)(&Xs[kk][8 * tn + 4]);
            ulonglong2 w01 = *(const ulonglong2*)(&Ws[kk][8 * tm]);
            ulonglong2 w23 = *(const ulonglong2*)(&Ws[kk][8 * tm + 4]);
            pf2 wp[4] = {w01.x, w01.y, w23.x, w23.y};
#pragma unroll
            for (int i = 0; i < 8; i++) {
                pf2 xb = pack2(xv[i], xv[i]);
#pragma unroll
                for (int jp = 0; jp < 4; jp++)
                    acc2[i][jp] = ffma2(xb, wp[jp], acc2[i][jp]);
            }
        }
        __syncthreads();
    }

#pragma unroll
    for (int i = 0; i < 8; i++) {
        const int n  = n0 + 8 * tn + i;
        const int bb = n >> 10;
        const int s  = n & 1023;
#pragma unroll
        for (int jp = 0; jp < 4; jp++) {
            float lo, hi;
            unpack2(acc2[i][jp], lo, hi);
            int m = m0 + 8 * tm + 2 * jp;
            {
                const int hh = m >> 6, d = m & 63;
                out[(((size_t)bb * NHEADS + hh) * SEQ + s) * HDIM + d] = lo + bias[m];
            }
            m++;
            {
                const int hh = m >> 6, d = m & 63;
                out[(((size_t)bb * NHEADS + hh) * SEQ + s) * HDIM + d] = hi + bias[m];
            }
        }
    }
}

// ---------------------------------------------------------------------------
// Fused attention, flash-style, d-major smem + packed f32x2.
// q_t/k_t/e_t stored [d][row] (stride 68/132): conflict-free LDS.128 reads.
// p_t stored [r][l] (stride 68): PV reads p as broadcast pair, v as float4.
// score[l,r] = q·k + q·E + k·E with E row = band[4(tl-tr)+60 + (i-j+3)].
// ---------------------------------------------------------------------------
__global__ __launch_bounds__(256, 2) void attn_kernel(
    const float* __restrict__ mask,   // [B,1,1,S]
    const float* __restrict__ E,      // [2047, 64]
    float* __restrict__ out)          // [B, S, H]
{
    extern __shared__ float sm[];
    float* q_t = sm;                    // [64 d][68]  (col = l)
    float* k_t = sm + 64 * 68;          // [64 d][68]  (col = r)
    float* v_s = sm + 2 * 64 * 68;      // [64 r][68]  (col = d)
    float* p_t = sm + 3 * 64 * 68;      // [64 r][68]  (col = l)
    float* e_t = sm + 4 * 64 * 68;      // [64 d][132] (col = band row 0..126)

    const int t  = threadIdx.x;
    const int tl = t >> 4;              // 0..15 (l group)
    const int tr = t & 15;              // 0..15 (r / d group)
    const int l0 = blockIdx.x * 64;
    const int h  = blockIdx.y;
    const int b  = blockIdx.z;

    const float* __restrict__ qg = g_q + (((size_t)b * NHEADS + h) * SEQ + l0) * HDIM;

    // Q transpose load (once): lane = row -> conflict-free scalar stores
#pragma unroll
    for (int it = 0; it < 4; ++it) {
        int eid = t + it * 256;          // 0..1023
        int r   = eid & 63;
        int c4  = (eid >> 6) << 2;
        float4 a = *(const float4*)(qg + r * 64 + c4);
        q_t[(c4 + 0) * 68 + r] = a.x; q_t[(c4 + 1) * 68 + r] = a.y;
        q_t[(c4 + 2) * 68 + r] = a.z; q_t[(c4 + 3) * 68 + r] = a.w;
    }

    pf2 acc2[2][4];                      // [l-pair][d col j]
    float mrow[4], lrow[4];
#pragma unroll
    for (int i = 0; i < 4; i++) { mrow[i] = -INFINITY; lrow[i] = 0.0f; }
#pragma unroll
    for (int ip = 0; ip < 2; ip++)
#pragma unroll
        for (int j = 0; j < 4; j++) acc2[ip][j] = 0ull;

    const float LOG2E = 1.4426950408889634f;

    const float* qp = q_t + 4 * tl;
    const float* kp = k_t + 4 * tr;
    const float* ep = e_t + 4 * (tl - tr) + 60;   // >= 0
    const float* pp = p_t + 4 * tl;
    const float* vp = v_s + 4 * tr;

    for (int rt = 0; rt < 16; ++rt) {
        const int r0 = rt * 64;
        __syncthreads();   // previous iter's consumers done with k/v/e/p

        const float* __restrict__ kg = g_k + (((size_t)b * NHEADS + h) * SEQ + r0) * HDIM;
        const float* __restrict__ vg = g_v + (((size_t)b * NHEADS + h) * SEQ + r0) * HDIM;

        // K transposed, V row-major
#pragma unroll
        for (int it = 0; it < 4; ++it) {
            int eid = t + it * 256;
            {
                int r  = eid & 63;
                int c4 = (eid >> 6) << 2;
                float4 a = *(const float4*)(kg + r * 64 + c4);
                k_t[(c4 + 0) * 68 + r] = a.x; k_t[(c4 + 1) * 68 + r] = a.y;
                k_t[(c4 + 2) * 68 + r] = a.z; k_t[(c4 + 3) * 68 + r] = a.w;
            }
            {
                int row = eid >> 4;
                int c4  = (eid & 15) << 2;
                float4 c = *(const float4*)(vg + row * 64 + c4);
                *(float4*)(&v_s[row * 68 + c4]) = c;
            }
        }
        // E band transposed: rows [l0-r0+960 .. +126]
        const int e_row0 = l0 - r0 + 960;
#pragma unroll
        for (int it = 0; it < 8; ++it) {
            int eid = t + it * 256;      // 0..2047
            int r   = eid & 127;
            int c4  = (eid >> 7) << 2;
            if (r < 127) {
                float4 a = *(const float4*)(E + (size_t)(e_row0 + r) * 64 + c4);
                e_t[(c4 + 0) * 132 + r] = a.x; e_t[(c4 + 1) * 132 + r] = a.y;
                e_t[(c4 + 2) * 132 + r] = a.z; e_t[(c4 + 3) * 132 + r] = a.w;
            }
        }
        __syncthreads();

        // --- scores (packed along l-pairs) ---
        pf2 s2[2][4];
#pragma unroll
        for (int ip = 0; ip < 2; ip++)
#pragma unroll
            for (int j = 0; j < 4; j++) s2[ip][j] = 0ull;

#pragma unroll 2
        for (int d = 0; d < 64; ++d) {
            ulonglong2 q2 = *(const ulonglong2*)(qp + d * 68);
            float4  kv = *(const float4*)(kp + d * 68);
            float4  e0 = *(const float4*)(ep + d * 132);
            float4  e1 = *(const float4*)(ep + d * 132 + 4);
            pf2 qpd[2] = {q2.x, q2.y};
            pf2 kb[4]  = {pack2(kv.x, kv.x), pack2(kv.y, kv.y),
                          pack2(kv.z, kv.z), pack2(kv.w, kv.w)};
            float ev[8] = {e0.x, e0.y, e0.z, e0.w, e1.x, e1.y, e1.z, e1.w};
            pf2 evp[6];
#pragma unroll
            for (int c = 0; c < 6; c++) evp[c] = pack2(ev[c], ev[c + 1]);
#pragma unroll
            for (int ip = 0; ip < 2; ip++)
#pragma unroll
                for (int j = 0; j < 4; j++) {
                    const int c = 2 * ip - j + 3;   // 0..5
                    s2[ip][j] = ffma2(qpd[ip], kb[j],  s2[ip][j]);
                    s2[ip][j] = ffma2(qpd[ip], evp[c], s2[ip][j]);
                    s2[ip][j] = ffma2(kb[j],   evp[c], s2[ip][j]);
                }
        }

        // unpack, scale + mask (base-2 domain)
        float s[4][4];
#pragma unroll
        for (int ip = 0; ip < 2; ip++)
#pragma unroll
            for (int j = 0; j < 4; j++)
                unpack2(s2[ip][j], s[2 * ip][j], s[2 * ip + 1][j]);
        float mk[4];
#pragma unroll
        for (int j = 0; j < 4; j++) mk[j] = mask[b * SEQ + r0 + 4 * tr + j];
#pragma unroll
        for (int i = 0; i < 4; i++)
#pragma unroll
            for (int j = 0; j < 4; j++)
                s[i][j] = (s[i][j] * 0.125f + mk[j]) * LOG2E;

        // row max: thread-local then across the 16 lanes of the row group
        float rmax[4];
#pragma unroll
        for (int i = 0; i < 4; i++)
            rmax[i] = fmaxf(fmaxf(s[i][0], s[i][1]), fmaxf(s[i][2], s[i][3]));
#pragma unroll
        for (int off = 8; off >= 1; off >>= 1)
#pragma unroll
            for (int i = 0; i < 4; i++)
                rmax[i] = fmaxf(rmax[i], __shfl_xor_sync(0xffffffffu, rmax[i], off));

        float p[4][4], rs[4], corr[4];
#pragma unroll
        for (int i = 0; i < 4; i++) {
            float mnew = fmaxf(mrow[i], rmax[i]);
            corr[i] = exp2f(mrow[i] - mnew);
            mrow[i] = mnew;
            float sum = 0.0f;
#pragma unroll
            for (int j = 0; j < 4; j++) { p[i][j] = exp2f(s[i][j] - mnew); sum += p[i][j]; }
            rs[i] = sum;
            lrow[i] *= corr[i];
        }
#pragma unroll
        for (int off = 8; off >= 1; off >>= 1)
#pragma unroll
            for (int i = 0; i < 4; i++)
                rs[i] += __shfl_xor_sync(0xffffffffu, rs[i], off);
#pragma unroll
        for (int i = 0; i < 4; i++) lrow[i] += rs[i];

        // rescale packed accumulators
        {
            pf2 c01 = pack2(corr[0], corr[1]);
            pf2 c23 = pack2(corr[2], corr[3]);
#pragma unroll
            for (int j = 0; j < 4; j++) {
                acc2[0][j] = mul2(acc2[0][j], c01);
                acc2[1][j] = mul2(acc2[1][j], c23);
            }
        }

        // store P as [r][l] (one 16B store per j)
#pragma unroll
        for (int j = 0; j < 4; j++) {
            ulonglong2 pd;
            pd.x = pack2(p[0][j], p[1][j]);
            pd.y = pack2(p[2][j], p[3][j]);
            *(ulonglong2*)(&p_t[(4 * tr + j) * 68 + 4 * tl]) = pd;
        }
        __syncthreads();   // p_t complete before PV reads all columns

        // --- PV: acc2[ip][j] over (l pair, d = 4*tr + j) ---
#pragma unroll 2
        for (int r = 0; r < 64; ++r) {
            ulonglong2 p2 = *(const ulonglong2*)(pp + r * 68);
            float4  vv = *(const float4*)(vp + r * 68);
            pf2 vb[4] = {pack2(vv.x, vv.x), pack2(vv.y, vv.y),
                         pack2(vv.z, vv.z), pack2(vv.w, vv.w)};
#pragma unroll
            for (int j = 0; j < 4; j++) {
                acc2[0][j] = ffma2(p2.x, vb[j], acc2[0][j]);
                acc2[1][j] = ffma2(p2.y, vb[j], acc2[1][j]);
            }
        }
    }

    // epilogue: normalize + write [B, S, H], float4 per row
    float o[4][4];
#pragma unroll
    for (int ip = 0; ip < 2; ip++)
#pragma unroll
        for (int j = 0; j < 4; j++)
            unpack2(acc2[ip][j], o[2 * ip][j], o[2 * ip + 1][j]);
#pragma unroll
    for (int i = 0; i < 4; i++) {
        const float inv = 1.0f / lrow[i];
        float4 ov = make_float4(o[i][0] * inv, o[i][1] * inv,
                                o[i][2] * inv, o[i][3] * inv);
        *(float4*)(out + ((size_t)b * SEQ + l0 + 4 * tl + i) * HID + h * HDIM + 4 * tr) = ov;
    }
}

// ---------------------------------------------------------------------------
extern "C" void kernel_launch(void* const* d_in, const int* in_sizes, int n_in,
                              void* d_out, int out_size)
{
    const float* hs   = (const float*)d_in[0];
    const float* mask = (const float*)d_in[1];
    const float* Wq   = (const float*)d_in[2];
    const float* bq   = (const float*)d_in[3];
    const float* Wk   = (const float*)d_in[4];
    const float* bk   = (const float*)d_in[5];
    const float* Wv   = (const float*)d_in[6];
    const float* bv   = (const float*)d_in[7];
    const float* dist = (const float*)d_in[8];
    float* out = (float*)d_out;

    (void)in_sizes; (void)n_in; (void)out_size;

    dim3 g1(BATCH * SEQ / 128, HID / 128, 3);
    qkv_proj_kernel<<<g1, 256>>>(hs, Wq, bq, Wk, bk, Wv, bv);

    const int smem_bytes = (4 * 64 * 68 + 64 * 132) * (int)sizeof(float);  // 103,424 B
    cudaFuncSetAttribute(attn_kernel, cudaFuncAttributeMaxDynamicSharedMemorySize,
                         smem_bytes);
    dim3 g2(SEQ / 64, NHEADS, BATCH);
    attn_kernel<<<g2, 256, smem_bytes>>>(mask, dist, out);
}

// round 16
// speedup vs baseline: 1.0004x; 1.0004x over previous
#include <cuda_runtime.h>
#include <math.h>

#define NHEADS 12
#define HDIM   64
#define BATCH  4
#define SEQ    1024
#define HID    768

// Scratch for projected Q/K/V in [B, h, S, d] layout
__device__ float g_q[BATCH * NHEADS * SEQ * HDIM];
__device__ float g_k[BATCH * NHEADS * SEQ * HDIM];
__device__ float g_v[BATCH * NHEADS * SEQ * HDIM];

// ---------------------------------------------------------------------------
// Packed f32x2 helpers (Blackwell FFMA2 path — PTX only).
// Packed pair carried as unsigned long long (the "l" constraint is integer).
// ---------------------------------------------------------------------------
typedef unsigned long long pf2;

__device__ __forceinline__ pf2 ffma2(pf2 a, pf2 b, pf2 c) {
    pf2 d; asm("fma.rn.f32x2 %0, %1, %2, %3;" : "=l"(d) : "l"(a), "l"(b), "l"(c)); return d;
}
__device__ __forceinline__ pf2 mul2(pf2 a, pf2 b) {
    pf2 d; asm("mul.rn.f32x2 %0, %1, %2;" : "=l"(d) : "l"(a), "l"(b)); return d;
}
__device__ __forceinline__ pf2 pack2(float lo, float hi) {
    pf2 d; asm("mov.b64 %0, {%1, %2};" : "=l"(d) : "f"(lo), "f"(hi)); return d;
}
__device__ __forceinline__ void unpack2(pf2 d, float& lo, float& hi) {
    asm("mov.b64 {%0, %1}, %2;" : "=f"(lo), "=f"(hi) : "l"(d));
}

// ---------------------------------------------------------------------------
// QKV projection: out[n, m] = sum_k X[n,k] * W[m,k] + b[m]
// 128x128 tile, K-step 16, 256 threads, 8x8 micro-tile, f32x2 packed FMA.
// ---------------------------------------------------------------------------
__global__ __launch_bounds__(256) void qkv_proj_kernel(
    const float* __restrict__ X,
    const float* __restrict__ Wq, const float* __restrict__ bq,
    const float* __restrict__ Wk, const float* __restrict__ bk,
    const float* __restrict__ Wv, const float* __restrict__ bv)
{
    __shared__ float Xs[16][132];
    __shared__ float Ws[16][132];

    const int z = blockIdx.z;
    const float* __restrict__ W    = (z == 0) ? Wq : ((z == 1) ? Wk : Wv);
    const float* __restrict__ bias = (z == 0) ? bq : ((z == 1) ? bk : bv);
    float* __restrict__ out        = (z == 0) ? g_q : ((z == 1) ? g_k : g_v);

    const int n0 = blockIdx.x * 128;
    const int m0 = blockIdx.y * 128;
    const int t  = threadIdx.x;
    const int tn = t & 15;
    const int tm = t >> 4;

    pf2 acc2[8][4];   // [i][m-pair]; 0ull == (0f, 0f)
#pragma unroll
    for (int i = 0; i < 8; i++)
#pragma unroll
        for (int jp = 0; jp < 4; jp++) acc2[i][jp] = 0ull;

    for (int k0 = 0; k0 < HID; k0 += 16) {
#pragma unroll
        for (int it = 0; it < 2; ++it) {
            int id  = t + it * 256;
            int row = id >> 2;
            int kq  = (id & 3) << 2;
            float4 xv = *(const float4*)(X + (size_t)(n0 + row) * HID + k0 + kq);
            Xs[kq + 0][row] = xv.x; Xs[kq + 1][row] = xv.y;
            Xs[kq + 2][row] = xv.z; Xs[kq + 3][row] = xv.w;
            float4 wv = *(const float4*)(W + (size_t)(m0 + row) * HID + k0 + kq);
            Ws[kq + 0][row] = wv.x; Ws[kq + 1][row] = wv.y;
            Ws[kq + 2][row] = wv.z; Ws[kq + 3][row] = wv.w;
        }
        __syncthreads();

#pragma unroll
        for (int kk = 0; kk < 16; ++kk) {
            float xv[8];
            *(float4*)(xv)     = *(const float4*)(&Xs[kk][8 * tn]);
            *(float4*)(xv + 4) = *(const float4*)(&Xs[kk][8 * tn + 4]);
            ulonglong2 w01 = *(const ulonglong2*)(&Ws[kk][8 * tm]);
            ulonglong2 w23 = *(const ulonglong2*)(&Ws[kk][8 * tm + 4]);
            pf2 wp[4] = {w01.x, w01.y, w23.x, w23.y};
#pragma unroll
            for (int i = 0; i < 8; i++) {
                pf2 xb = pack2(xv[i], xv[i]);
#pragma unroll
                for (int jp = 0; jp < 4; jp++)
                    acc2[i][jp] = ffma2(xb, wp[jp], acc2[i][jp]);
            }
        }
        __syncthreads();
    }

#pragma unroll
    for (int i = 0; i < 8; i++) {
        const int n  = n0 + 8 * tn + i;
        const int bb = n >> 10;
        const int s  = n & 1023;
#pragma unroll
        for (int jp = 0; jp < 4; jp++) {
            float lo, hi;
            unpack2(acc2[i][jp], lo, hi);
            int m = m0 + 8 * tm + 2 * jp;
            {
                const int hh = m >> 6, d = m & 63;
                out[(((size_t)bb * NHEADS + hh) * SEQ + s) * HDIM + d] = lo + bias[m];
            }
            m++;
            {
                const int hh = m >> 6, d = m & 63;
                out[(((size_t)bb * NHEADS + hh) * SEQ + s) * HDIM + d] = hi + bias[m];
            }
        }
    }
}

// ---------------------------------------------------------------------------
// Fused attention, flash-style, d-major smem + packed f32x2.
// q_t/k_t/e_t stored [d][row] (stride 68/132): conflict-free LDS.128 reads.
// p_t stored [r][l] (stride 68): PV reads p as broadcast pair, v as float4.
// score[l,r] = q·k + q·E + k·E with E row = band[4(tl-tr)+60 + (i-j+3)].
// ---------------------------------------------------------------------------
__global__ __launch_bounds__(256, 2) void attn_kernel(
    const float* __restrict__ mask,   // [B,1,1,S]
    const float* __restrict__ E,      // [2047, 64]
    float* __restrict__ out)          // [B, S, H]
{
    extern __shared__ float sm[];
    float* q_t = sm;                    // [64 d][68]  (col = l)
    float* k_t = sm + 64 * 68;          // [64 d][68]  (col = r)
    float* v_s = sm + 2 * 64 * 68;      // [64 r][68]  (col = d)
    float* p_t = sm + 3 * 64 * 68;      // [64 r][68]  (col = l)
    float* e_t = sm + 4 * 64 * 68;      // [64 d][132] (col = band row 0..126)

    const int t  = threadIdx.x;
    const int tl = t >> 4;              // 0..15 (l group)
    const int tr = t & 15;              // 0..15 (r / d group)
    const int l0 = blockIdx.x * 64;
    const int h  = blockIdx.y;
    const int b  = blockIdx.z;

    const float* __restrict__ qg = g_q + (((size_t)b * NHEADS + h) * SEQ + l0) * HDIM;

    // Q transpose load (once): lane = row -> conflict-free scalar stores
#pragma unroll
    for (int it = 0; it < 4; ++it) {
        int eid = t + it * 256;          // 0..1023
        int r   = eid & 63;
        int c4  = (eid >> 6) << 2;
        float4 a = *(const float4*)(qg + r * 64 + c4);
        q_t[(c4 + 0) * 68 + r] = a.x; q_t[(c4 + 1) * 68 + r] = a.y;
        q_t[(c4 + 2) * 68 + r] = a.z; q_t[(c4 + 3) * 68 + r] = a.w;
    }

    pf2 acc2[2][4];                      // [l-pair][d col j]
    float mrow[4], lrow[4];
#pragma unroll
    for (int i = 0; i < 4; i++) { mrow[i] = -INFINITY; lrow[i] = 0.0f; }
#pragma unroll
    for (int ip = 0; ip < 2; ip++)
#pragma unroll
        for (int j = 0; j < 4; j++) acc2[ip][j] = 0ull;

    const float LOG2E = 1.4426950408889634f;

    const float* qp = q_t + 4 * tl;
    const float* kp = k_t + 4 * tr;
    const float* ep = e_t + 4 * (tl - tr) + 60;   // >= 0
    const float* pp = p_t + 4 * tl;
    const float* vp = v_s + 4 * tr;

    for (int rt = 0; rt < 16; ++rt) {
        const int r0 = rt * 64;
        __syncthreads();   // previous iter's consumers done with k/v/e/p

        const float* __restrict__ kg = g_k + (((size_t)b * NHEADS + h) * SEQ + r0) * HDIM;
        const float* __restrict__ vg = g_v + (((size_t)b * NHEADS + h) * SEQ + r0) * HDIM;

        // K transposed, V row-major
#pragma unroll
        for (int it = 0; it < 4; ++it) {
            int eid = t + it * 256;
            {
                int r  = eid & 63;
                int c4 = (eid >> 6) << 2;
                float4 a = *(const float4*)(kg + r * 64 + c4);
                k_t[(c4 + 0) * 68 + r] = a.x; k_t[(c4 + 1) * 68 + r] = a.y;
                k_t[(c4 + 2) * 68 + r] = a.z; k_t[(c4 + 3) * 68 + r] = a.w;
            }
            {
                int row = eid >> 4;
                int c4  = (eid & 15) << 2;
                float4 c = *(const float4*)(vg + row * 64 + c4);
                *(float4*)(&v_s[row * 68 + c4]) = c;
            }
        }
        // E band transposed: rows [l0-r0+960 .. +126]
        const int e_row0 = l0 - r0 + 960;
#pragma unroll
        for (int it = 0; it < 8; ++it) {
            int eid = t + it * 256;      // 0..2047
            int r   = eid & 127;
            int c4  = (eid >> 7) << 2;
            if (r < 127) {
                float4 a = *(const float4*)(E + (size_t)(e_row0 + r) * 64 + c4);
                e_t[(c4 + 0) * 132 + r] = a.x; e_t[(c4 + 1) * 132 + r] = a.y;
                e_t[(c4 + 2) * 132 + r] = a.z; e_t[(c4 + 3) * 132 + r] = a.w;
            }
        }
        __syncthreads();

        // --- scores (packed along l-pairs) ---
        pf2 s2[2][4];
#pragma unroll
        for (int ip = 0; ip < 2; ip++)
#pragma unroll
            for (int j = 0; j < 4; j++) s2[ip][j] = 0ull;

#pragma unroll 2
        for (int d = 0; d < 64; ++d) {
            ulonglong2 q2 = *(const ulonglong2*)(qp + d * 68);
            float4  kv = *(const float4*)(kp + d * 68);
            float4  e0 = *(const float4*)(ep + d * 132);
            float4  e1 = *(const float4*)(ep + d * 132 + 4);
            pf2 qpd[2] = {q2.x, q2.y};
            pf2 kb[4]  = {pack2(kv.x, kv.x), pack2(kv.y, kv.y),
                          pack2(kv.z, kv.z), pack2(kv.w, kv.w)};
            float ev[8] = {e0.x, e0.y, e0.z, e0.w, e1.x, e1.y, e1.z, e1.w};
            pf2 evp[6];
#pragma unroll
            for (int c = 0; c < 6; c++) evp[c] = pack2(ev[c], ev[c + 1]);
#pragma unroll
            for (int ip = 0; ip < 2; ip++)
#pragma unroll
                for (int j = 0; j < 4; j++) {
                    const int c = 2 * ip - j + 3;   // 0..5
                    s2[ip][j] = ffma2(qpd[ip], kb[j],  s2[ip][j]);
                    s2[ip][j] = ffma2(qpd[ip], evp[c], s2[ip][j]);
                    s2[ip][j] = ffma2(kb[j],   evp[c], s2[ip][j]);
                }
        }

        // unpack, scale + mask (base-2 domain)
        float s[4][4];
#pragma unroll
        for (int ip = 0; ip < 2; ip++)
#pragma unroll
            for (int j = 0; j < 4; j++)
                unpack2(s2[ip][j], s[2 * ip][j], s[2 * ip + 1][j]);
        float mk[4];
#pragma unroll
        for (int j = 0; j < 4; j++) mk[j] = mask[b * SEQ + r0 + 4 * tr + j];
#pragma unroll
        for (int i = 0; i < 4; i++)
#pragma unroll
            for (int j = 0; j < 4; j++)
                s[i][j] = (s[i][j] * 0.125f + mk[j]) * LOG2E;

        // row max: thread-local then across the 16 lanes of the row group
        float rmax[4];
#pragma unroll
        for (int i = 0; i < 4; i++)
            rmax[i] = fmaxf(fmaxf(s[i][0], s[i][1]), fmaxf(s[i][2], s[i][3]));
#pragma unroll
        for (int off = 8; off >= 1; off >>= 1)
#pragma unroll
            for (int i = 0; i < 4; i++)
                rmax[i] = fmaxf(rmax[i], __shfl_xor_sync(0xffffffffu, rmax[i], off));

        float p[4][4], rs[4], corr[4];
#pragma unroll
        for (int i = 0; i < 4; i++) {
            float mnew = fmaxf(mrow[i], rmax[i]);
            corr[i] = exp2f(mrow[i] - mnew);
            mrow[i] = mnew;
            float sum = 0.0f;
#pragma unroll
            for (int j = 0; j < 4; j++) { p[i][j] = exp2f(s[i][j] - mnew); sum += p[i][j]; }
            rs[i] = sum;
            lrow[i] *= corr[i];
        }
#pragma unroll
        for (int off = 8; off >= 1; off >>= 1)
#pragma unroll
            for (int i = 0; i < 4; i++)
                rs[i] += __shfl_xor_sync(0xffffffffu, rs[i], off);
#pragma unroll
        for (int i = 0; i < 4; i++) lrow[i] += rs[i];

        // rescale packed accumulators
        {
            pf2 c01 = pack2(corr[0], corr[1]);
            pf2 c23 = pack2(corr[2], corr[3]);
#pragma unroll
            for (int j = 0; j < 4; j++) {
                acc2[0][j] = mul2(acc2[0][j], c01);
                acc2[1][j] = mul2(acc2[1][j], c23);
            }
        }

        // store P as [r][l] (one 16B store per j)
#pragma unroll
        for (int j = 0; j < 4; j++) {
            ulonglong2 pd;
            pd.x = pack2(p[0][j], p[1][j]);
            pd.y = pack2(p[2][j], p[3][j]);
            *(ulonglong2*)(&p_t[(4 * tr + j) * 68 + 4 * tl]) = pd;
        }
        __syncthreads();   // p_t complete before PV reads all columns

        // --- PV: acc2[ip][j] over (l pair, d = 4*tr + j) ---
#pragma unroll 2
        for (int r = 0; r < 64; ++r) {
            ulonglong2 p2 = *(const ulonglong2*)(pp + r * 68);
            float4  vv = *(const float4*)(vp + r * 68);
            pf2 vb[4] = {pack2(vv.x, vv.x), pack2(vv.y, vv.y),
                         pack2(vv.z, vv.z), pack2(vv.w, vv.w)};
#pragma unroll
            for (int j = 0; j < 4; j++) {
                acc2[0][j] = ffma2(p2.x, vb[j], acc2[0][j]);
                acc2[1][j] = ffma2(p2.y, vb[j], acc2[1][j]);
            }
        }
    }

    // epilogue: normalize + write [B, S, H], float4 per row
    float o[4][4];
#pragma unroll
    for (int ip = 0; ip < 2; ip++)
#pragma unroll
        for (int j = 0; j < 4; j++)
            unpack2(acc2[ip][j], o[2 * ip][j], o[2 * ip + 1][j]);
#pragma unroll
    for (int i = 0; i < 4; i++) {
        const float inv = 1.0f / lrow[i];
        float4 ov = make_float4(o[i][0] * inv, o[i][1] * inv,
                                o[i][2] * inv, o[i][3] * inv);
        *(float4*)(out + ((size_t)b * SEQ + l0 + 4 * tl + i) * HID + h * HDIM + 4 * tr) = ov;
    }
}

// ---------------------------------------------------------------------------
extern "C" void kernel_launch(void* const* d_in, const int* in_sizes, int n_in,
                              void* d_out, int out_size)
{
    const float* hs   = (const float*)d_in[0];
    const float* mask = (const float*)d_in[1];
    const float* Wq   = (const float*)d_in[2];
    const float* bq   = (const float*)d_in[3];
    const float* Wk   = (const float*)d_in[4];
    const float* bk   = (const float*)d_in[5];
    const float* Wv   = (const float*)d_in[6];
    const float* bv   = (const float*)d_in[7];
    const float* dist = (const float*)d_in[8];
    float* out = (float*)d_out;

    (void)in_sizes; (void)n_in; (void)out_size;

    dim3 g1(BATCH * SEQ / 128, HID / 128, 3);
    qkv_proj_kernel<<<g1, 256>>>(hs, Wq, bq, Wk, bk, Wv, bv);

    const int smem_bytes = (4 * 64 * 68 + 64 * 132) * (int)sizeof(float);  // 103,424 B
    cudaFuncSetAttribute(attn_kernel, cudaFuncAttributeMaxDynamicSharedMemorySize,
                         smem_bytes);
    dim3 g2(SEQ / 64, NHEADS, BATCH);
    attn_kernel<<<g2, 256, smem_bytes>>>(mask, dist, out);
}